// round 1
// baseline (speedup 1.0000x reference)
#include <cuda_runtime.h>
#include <math.h>

#define SEQ  2048
#define BT   4
#define XD   16
#define DM   256
#define NHD  8
#define DH   32
#define DFF  512
#define NL   2
#define ROWS (SEQ*BT)

// ---------------- scratch (static device globals; no allocation) -------------
__device__ float g_h   [ROWS*DM];
__device__ float g_qkv [ROWS*3*DM];
__device__ float g_q   [ROWS*DM];
__device__ float g_k   [ROWS*DM];
__device__ float g_v   [ROWS*DM];
__device__ float g_att [ROWS*DM];
__device__ float g_tmp [ROWS*DM];
__device__ float g_tmp2[ROWS*DM];
__device__ float g_ff  [ROWS*DFF];

// ---------------- embed: tokens = xenc(x) (+ yenc(y) for s < M) --------------
__global__ void embed_kernel(const float* __restrict__ x, const float* __restrict__ y,
                             const int* __restrict__ sep,
                             const float* __restrict__ xw, const float* __restrict__ xb,
                             const float* __restrict__ yw, const float* __restrict__ yb,
                             float* __restrict__ h)
{
    int row = blockIdx.x;           // s*BT + b
    int s = row >> 2, b = row & 3;
    int d = threadIdx.x;            // 0..255
    __shared__ float xs[XD];
    if (threadIdx.x < XD) xs[threadIdx.x] = x[(s*BT + b)*XD + threadIdx.x];
    __syncthreads();
    float acc = xb[d];
    #pragma unroll
    for (int j = 0; j < XD; j++) acc += xs[j] * xw[d*XD + j];
    int M_ = *sep;
    if (s < M_) acc += y[s*BT + b] * yw[d] + yb[d];
    h[row*DM + d] = acc;
}

// ---------------- generic SGEMM: C = A (Mr x K) * W^T (N x K) + bias ---------
__device__ __forceinline__ float gelu_exact(float v) {
    return 0.5f * v * (1.0f + erff(v * 0.70710678118654752f));
}

template<int ACT>   // 0 = none, 1 = exact gelu
__global__ __launch_bounds__(256, 2)
void gemm_bias(const float* __restrict__ A, const float* __restrict__ W,
               const float* __restrict__ bias, float* __restrict__ C,
               int N, int Kdim)
{
    __shared__ float As[8][128];
    __shared__ float Ws[8][128];
    const int tid = threadIdx.x;
    const int m0 = blockIdx.y * 128;
    const int n0 = blockIdx.x * 128;
    const int lm = tid >> 1;          // 0..127
    const int lk = (tid & 1) * 4;     // 0 or 4
    const int rm = (tid >> 4) * 8;
    const int rn = (tid & 15) * 8;

    float acc[8][8];
    #pragma unroll
    for (int i = 0; i < 8; i++)
        #pragma unroll
        for (int j = 0; j < 8; j++) acc[i][j] = 0.f;

    for (int k0 = 0; k0 < Kdim; k0 += 8) {
        float4 a4 = *(const float4*)&A[(size_t)(m0 + lm) * Kdim + k0 + lk];
        float4 w4 = *(const float4*)&W[(size_t)(n0 + lm) * Kdim + k0 + lk];
        As[lk+0][lm] = a4.x; As[lk+1][lm] = a4.y; As[lk+2][lm] = a4.z; As[lk+3][lm] = a4.w;
        Ws[lk+0][lm] = w4.x; Ws[lk+1][lm] = w4.y; Ws[lk+2][lm] = w4.z; Ws[lk+3][lm] = w4.w;
        __syncthreads();
        #pragma unroll
        for (int kk = 0; kk < 8; kk++) {
            float ar[8], br[8];
            *(float4*)(ar)     = *(const float4*)&As[kk][rm];
            *(float4*)(ar + 4) = *(const float4*)&As[kk][rm + 4];
            *(float4*)(br)     = *(const float4*)&Ws[kk][rn];
            *(float4*)(br + 4) = *(const float4*)&Ws[kk][rn + 4];
            #pragma unroll
            for (int i = 0; i < 8; i++)
                #pragma unroll
                for (int j = 0; j < 8; j++)
                    acc[i][j] += ar[i] * br[j];
        }
        __syncthreads();
    }

    float bj[8];
    #pragma unroll
    for (int j = 0; j < 8; j++) bj[j] = bias[n0 + rn + j];
    #pragma unroll
    for (int i = 0; i < 8; i++) {
        size_t base = (size_t)(m0 + rm + i) * N + n0 + rn;
        float4 v0, v1;
        float vals[8];
        #pragma unroll
        for (int j = 0; j < 8; j++) {
            float vv = acc[i][j] + bj[j];
            if (ACT == 1) vv = gelu_exact(vv);
            vals[j] = vv;
        }
        v0 = make_float4(vals[0], vals[1], vals[2], vals[3]);
        v1 = make_float4(vals[4], vals[5], vals[6], vals[7]);
        *(float4*)&C[base]     = v0;
        *(float4*)&C[base + 4] = v1;
    }
}

// ---------------- split qkv (ROWS x 768) -> q/k/v in (B, NH, SEQ, DH) --------
__global__ void split_heads(const float* __restrict__ qkv,
                            float* __restrict__ q, float* __restrict__ k,
                            float* __restrict__ v)
{
    int idx = blockIdx.x * blockDim.x + threadIdx.x;
    if (idx >= ROWS*DM) return;
    int dh = idx & 31;
    int s  = (idx >> 5) & (SEQ - 1);
    int hh = (idx >> 16) & (NHD - 1);       // idx/(32*2048) % 8
    int b  = idx >> 19;                     // idx/(32*2048*8)
    int src = (s*BT + b) * (3*DM) + hh*DH + dh;
    q[idx] = qkv[src];
    k[idx] = qkv[src + DM];
    v[idx] = qkv[src + 2*DM];
}

// ---------------- merge heads (B, NH, SEQ, DH) -> (ROWS x DM) ----------------
__global__ void merge_heads(const float* __restrict__ att, float* __restrict__ out)
{
    int idx = blockIdx.x * blockDim.x + threadIdx.x;
    if (idx >= ROWS*DM) return;
    int d   = idx & (DM - 1);
    int row = idx >> 8;
    int s = row >> 2, b = row & 3;
    int hh = d >> 5, dh = d & 31;
    out[idx] = att[(((size_t)(b*NHD + hh))*SEQ + s)*DH + dh];
}

// ---------------- flash-style attention ---------------------------------------
// keep = (k < M) | (q == k); scale 1/sqrt(32). Q tile 32, key chunks of 32.
__global__ __launch_bounds__(256)
void attn_kernel(const float* __restrict__ Q, const float* __restrict__ K,
                 const float* __restrict__ V, const int* __restrict__ sep,
                 float* __restrict__ O)
{
    const int b = blockIdx.z, h = blockIdx.y;
    const int q0 = blockIdx.x * 32;
    const size_t head_off = ((size_t)(b*NHD + h)) * SEQ * DH;
    const float* qb = Q + head_off;
    const float* kb = K + head_off;
    const float* vb = V + head_off;
    float*       ob = O + head_off;

    __shared__ float Qs[32][32];
    __shared__ float Ks[32][32];
    __shared__ float Vs[32][32];
    __shared__ float S [32][33];
    __shared__ float m_s[32], l_s[32], a_s[32];

    const int tid = threadIdx.x;
    {
        int e = tid * 4, r = e >> 5, dd = e & 31;
        *(float4*)&Qs[r][dd] = *(const float4*)&qb[(size_t)(q0 + r)*DH + dd];
    }
    if (tid < 32) { m_s[tid] = -1e30f; l_s[tid] = 0.f; }

    float acc0 = 0.f, acc1 = 0.f, acc2 = 0.f, acc3 = 0.f;
    const int qi = tid >> 3;
    const int c0 = (tid & 7) * 4;
    const int M_ = *sep;
    const int nch = (M_ + 31) >> 5;
    const float scale = 0.17677669529663687f;   // 1/sqrt(32)

    for (int c = 0; c <= nch; c++) {
        const bool diag = (c == nch);
        const int kbase = diag ? q0 : c * 32;
        __syncthreads();
        {
            int e = tid * 4, r = e >> 5, dd = e & 31;
            int key = kbase + r;
            float4 kv, vv;
            if (!diag && key >= M_) {
                kv = make_float4(0,0,0,0); vv = kv;
            } else {
                kv = *(const float4*)&kb[(size_t)key*DH + dd];
                vv = *(const float4*)&vb[(size_t)key*DH + dd];
            }
            *(float4*)&Ks[r][dd] = kv;
            *(float4*)&Vs[r][dd] = vv;
        }
        __syncthreads();

        #pragma unroll
        for (int u = 0; u < 4; u++) {
            int kj = c0 + u;
            int key = kbase + kj;
            bool ok = diag ? (key >= M_ && kj == qi) : (key < M_);
            float sv = -1e30f;
            if (ok) {
                float dot = 0.f;
                const float4* qr = (const float4*)Qs[qi];
                const float4* kr = (const float4*)Ks[kj];
                #pragma unroll
                for (int d4 = 0; d4 < 8; d4++) {
                    float4 a = qr[d4], bb = kr[d4];
                    dot += a.x*bb.x + a.y*bb.y + a.z*bb.z + a.w*bb.w;
                }
                sv = dot * scale;
            }
            S[qi][kj] = sv;
        }
        __syncthreads();

        if (tid < 32) {
            float mold = m_s[tid];
            float mx = mold;
            #pragma unroll
            for (int j = 0; j < 32; j++) mx = fmaxf(mx, S[tid][j]);
            if (mx <= -1e29f) {
                a_s[tid] = 1.f;
                #pragma unroll
                for (int j = 0; j < 32; j++) S[tid][j] = 0.f;
            } else {
                float al = expf(mold - mx);
                float ls = 0.f;
                #pragma unroll
                for (int j = 0; j < 32; j++) {
                    float p = expf(S[tid][j] - mx);
                    S[tid][j] = p;
                    ls += p;
                }
                m_s[tid] = mx;
                l_s[tid] = l_s[tid] * al + ls;
                a_s[tid] = al;
            }
        }
        __syncthreads();

        float al = a_s[qi];
        acc0 *= al; acc1 *= al; acc2 *= al; acc3 *= al;
        #pragma unroll
        for (int kj2 = 0; kj2 < 32; kj2++) {
            float p = S[qi][kj2];
            acc0 += p * Vs[kj2][c0 + 0];
            acc1 += p * Vs[kj2][c0 + 1];
            acc2 += p * Vs[kj2][c0 + 2];
            acc3 += p * Vs[kj2][c0 + 3];
        }
    }

    float inv = 1.f / l_s[qi];
    float4 r4 = make_float4(acc0*inv, acc1*inv, acc2*inv, acc3*inv);
    *(float4*)&ob[(size_t)(q0 + qi)*DH + c0] = r4;
}

// ---------------- residual add + layer norm (population var, eps 1e-5) -------
__global__ void add_ln_kernel(const float* __restrict__ resid,
                              const float* __restrict__ delta,
                              const float* __restrict__ g, const float* __restrict__ bb,
                              float* __restrict__ out)
{
    int row = blockIdx.x;
    int d = threadIdx.x;
    __shared__ float red[DM];
    __shared__ float mu_s, rstd_s;
    float v = resid[(size_t)row*DM + d] + delta[(size_t)row*DM + d];
    red[d] = v;
    __syncthreads();
    for (int off = 128; off > 0; off >>= 1) {
        if (d < off) red[d] += red[d + off];
        __syncthreads();
    }
    if (d == 0) mu_s = red[0] * (1.0f / DM);
    __syncthreads();
    float mu = mu_s;
    float c = v - mu;
    red[d] = c * c;
    __syncthreads();
    for (int off = 128; off > 0; off >>= 1) {
        if (d < off) red[d] += red[d + off];
        __syncthreads();
    }
    if (d == 0) rstd_s = rsqrtf(red[0] * (1.0f / DM) + 1e-5f);
    __syncthreads();
    out[(size_t)row*DM + d] = c * rstd_s * g[d] + bb[d];
}

// ---------------- final head: out[(s-M)*B+b] = hid . w2 + b2 -----------------
__global__ void head2_kernel(const float* __restrict__ hid, const float* __restrict__ w2,
                             const float* __restrict__ b2, const int* __restrict__ sep,
                             float* __restrict__ out)
{
    int row = blockIdx.x;
    int M_ = *sep;
    int s = row >> 2, b = row & 3;
    if (s < M_) return;
    float sum = 0.f;
    for (int t = threadIdx.x; t < DFF; t += 128)
        sum += hid[(size_t)row*DFF + t] * w2[t];
    for (int off = 16; off > 0; off >>= 1)
        sum += __shfl_down_sync(0xffffffffu, sum, off);
    __shared__ float ws[4];
    if ((threadIdx.x & 31) == 0) ws[threadIdx.x >> 5] = sum;
    __syncthreads();
    if (threadIdx.x == 0)
        out[(s - M_)*BT + b] = ws[0] + ws[1] + ws[2] + ws[3] + b2[0];
}

// =============================================================================
extern "C" void kernel_launch(void* const* d_in, const int* in_sizes, int n_in,
                              void* d_out, int out_size)
{
    (void)in_sizes; (void)n_in; (void)out_size;
    const float* x        = (const float*)d_in[0];
    const float* y        = (const float*)d_in[1];
    const int*   sep      = (const int*  )d_in[2];
    const float* xenc_w   = (const float*)d_in[3];
    const float* xenc_b   = (const float*)d_in[4];
    const float* yenc_w   = (const float*)d_in[5];
    const float* yenc_b   = (const float*)d_in[6];
    const float* in_proj_w= (const float*)d_in[7];
    const float* in_proj_b= (const float*)d_in[8];
    const float* out_proj_w=(const float*)d_in[9];
    const float* out_proj_b=(const float*)d_in[10];
    const float* ln1_g    = (const float*)d_in[11];
    const float* ln1_b    = (const float*)d_in[12];
    const float* lin1_w   = (const float*)d_in[13];
    const float* lin1_b   = (const float*)d_in[14];
    const float* lin2_w   = (const float*)d_in[15];
    const float* lin2_b   = (const float*)d_in[16];
    const float* ln2_g    = (const float*)d_in[17];
    const float* ln2_b    = (const float*)d_in[18];
    const float* head_w1  = (const float*)d_in[19];
    const float* head_b1  = (const float*)d_in[20];
    const float* head_w2  = (const float*)d_in[21];
    const float* head_b2  = (const float*)d_in[22];
    float* out = (float*)d_out;

    float *h, *qkv, *q, *k, *v, *att, *tmp, *tmp2, *ff;
    cudaGetSymbolAddress((void**)&h,    g_h);
    cudaGetSymbolAddress((void**)&qkv,  g_qkv);
    cudaGetSymbolAddress((void**)&q,    g_q);
    cudaGetSymbolAddress((void**)&k,    g_k);
    cudaGetSymbolAddress((void**)&v,    g_v);
    cudaGetSymbolAddress((void**)&att,  g_att);
    cudaGetSymbolAddress((void**)&tmp,  g_tmp);
    cudaGetSymbolAddress((void**)&tmp2, g_tmp2);
    cudaGetSymbolAddress((void**)&ff,   g_ff);

    // embed
    embed_kernel<<<ROWS, DM>>>(x, y, sep, xenc_w, xenc_b, yenc_w, yenc_b, h);

    const int elem_grid = (ROWS*DM + 255) / 256;

    for (int l = 0; l < NL; l++) {
        // QKV projection: (8192 x 256) @ (768 x 256)^T
        gemm_bias<0><<<dim3(3*DM/128, ROWS/128), 256>>>(
            h, in_proj_w + (size_t)l*3*DM*DM, in_proj_b + (size_t)l*3*DM, qkv, 3*DM, DM);
        split_heads<<<elem_grid, 256>>>(qkv, q, k, v);
        // attention
        attn_kernel<<<dim3(SEQ/32, NHD, BT), 256>>>(q, k, v, sep, att);
        merge_heads<<<elem_grid, 256>>>(att, tmp);
        // out projection
        gemm_bias<0><<<dim3(DM/128, ROWS/128), 256>>>(
            tmp, out_proj_w + (size_t)l*DM*DM, out_proj_b + (size_t)l*DM, tmp2, DM, DM);
        add_ln_kernel<<<ROWS, DM>>>(h, tmp2, ln1_g + (size_t)l*DM, ln1_b + (size_t)l*DM, h);
        // FF
        gemm_bias<1><<<dim3(DFF/128, ROWS/128), 256>>>(
            h, lin1_w + (size_t)l*DFF*DM, lin1_b + (size_t)l*DFF, ff, DFF, DM);
        gemm_bias<0><<<dim3(DM/128, ROWS/128), 256>>>(
            ff, lin2_w + (size_t)l*DM*DFF, lin2_b + (size_t)l*DM, tmp2, DM, DFF);
        add_ln_kernel<<<ROWS, DM>>>(h, tmp2, ln2_g + (size_t)l*DM, ln2_b + (size_t)l*DM, h);
    }

    // head: gelu(h @ head_w1^T + b1) over all rows (rows < M unused), then dot
    gemm_bias<1><<<dim3(DFF/128, ROWS/128), 256>>>(h, head_w1, head_b1, ff, DFF, DM);
    head2_kernel<<<ROWS, 128>>>(ff, head_w2, head_b2, sep, out);
}

// round 3
// speedup vs baseline: 1.0686x; 1.0686x over previous
#include <cuda_runtime.h>
#include <cstdint>
#include <math.h>

#define SEQ  2048
#define BT   4
#define XD   16
#define DM   256
#define NHD  8
#define DH   32
#define DFF  512
#define NL   2
#define ROWS (SEQ*BT)

// ---------------- scratch (static device globals; no allocation) -------------
__device__ float g_h   [ROWS*DM];
__device__ float g_qkv [ROWS*3*DM];
__device__ float g_q   [ROWS*DM];
__device__ float g_k   [ROWS*DM];
__device__ float g_v   [ROWS*DM];
__device__ float g_att [ROWS*DM];
__device__ float g_tmp [ROWS*DM];
__device__ float g_tmp2[ROWS*DM];
__device__ float g_ff  [ROWS*DFF];

// ---------------- embed: tokens = xenc(x) (+ yenc(y) for s < M) --------------
__global__ void embed_kernel(const float* __restrict__ x, const float* __restrict__ y,
                             const int* __restrict__ sep,
                             const float* __restrict__ xw, const float* __restrict__ xb,
                             const float* __restrict__ yw, const float* __restrict__ yb,
                             float* __restrict__ h)
{
    int row = blockIdx.x;           // s*BT + b
    int s = row >> 2, b = row & 3;
    int d = threadIdx.x;            // 0..255
    __shared__ float xs[XD];
    if (threadIdx.x < XD) xs[threadIdx.x] = x[(s*BT + b)*XD + threadIdx.x];
    __syncthreads();
    float acc = xb[d];
    #pragma unroll
    for (int j = 0; j < XD; j++) acc += xs[j] * xw[d*XD + j];
    int M_ = *sep;
    if (s < M_) acc += y[s*BT + b] * yw[d] + yb[d];
    h[row*DM + d] = acc;
}

// ---------------- helpers -----------------------------------------------------
__device__ __forceinline__ float gelu_exact(float v) {
    return 0.5f * v * (1.0f + erff(v * 0.70710678118654752f));
}
__device__ __forceinline__ uint32_t f2tf32(float f) {
    uint32_t r;
    asm("cvt.rna.tf32.f32 %0, %1;" : "=r"(r) : "f"(f));
    return r;
}
__device__ __forceinline__ void mma_tf32(float c[4], const uint32_t a[4], const uint32_t b[2]) {
    asm volatile(
        "mma.sync.aligned.m16n8k8.row.col.f32.tf32.tf32.f32 "
        "{%0,%1,%2,%3}, {%4,%5,%6,%7}, {%8,%9}, {%0,%1,%2,%3};\n"
        : "+f"(c[0]), "+f"(c[1]), "+f"(c[2]), "+f"(c[3])
        : "r"(a[0]), "r"(a[1]), "r"(a[2]), "r"(a[3]), "r"(b[0]), "r"(b[1]));
}

// ---------------- TF32 tensor-core GEMM: C = A (Mr x K) * W^T (N x K) + bias --
// block tile 128x128, BK=16, double-buffered smem, 8 warps of 64x32 warp tiles.
template<int ACT>   // 0 = none, 1 = exact gelu
__global__ __launch_bounds__(256)
void gemm_tc(const float* __restrict__ A, const float* __restrict__ W,
             const float* __restrict__ bias, float* __restrict__ C,
             int N, int Kdim, const int* __restrict__ sep_skip)
{
    const int m0 = blockIdx.y * 128;
    const int n0 = blockIdx.x * 128;
    if (sep_skip) {                               // head GEMM: skip blocks fully below M
        int M_ = *sep_skip;
        if (((m0 + 127) >> 2) < M_) return;
    }

    __shared__ uint32_t As[2][128][20];           // m-major, stride 20 (conflict-free frags)
    __shared__ uint32_t Bs[2][128][20];           // n-major, stride 20

    const int tid  = threadIdx.x;
    const int lane = tid & 31;
    const int warp = tid >> 5;
    const int grp  = lane >> 2;                   // 0..7
    const int qp   = lane & 3;                    // 0..3
    const int mw   = (warp >> 2) * 64;            // warp m offset (0 or 64)
    const int nw   = (warp & 3) * 32;             // warp n offset (0..96)

    // gmem load mapping: each thread loads 2 float4 for A and 2 for B per k-tile
    const int lr = tid >> 1;                      // 0..127 (row within tile)
    const int lc = (tid & 1) * 8;                 // 0 or 8 (k offset)

    float acc[4][4][4];
    #pragma unroll
    for (int mt = 0; mt < 4; mt++)
        #pragma unroll
        for (int nt = 0; nt < 4; nt++)
            #pragma unroll
            for (int e = 0; e < 4; e++) acc[mt][nt][e] = 0.f;

    const int nk = Kdim >> 4;

    // initial tile -> buf 0
    {
        float4 a0 = *(const float4*)&A[(size_t)(m0 + lr) * Kdim + lc];
        float4 a1 = *(const float4*)&A[(size_t)(m0 + lr) * Kdim + lc + 4];
        float4 b0 = *(const float4*)&W[(size_t)(n0 + lr) * Kdim + lc];
        float4 b1 = *(const float4*)&W[(size_t)(n0 + lr) * Kdim + lc + 4];
        uint4 ua0 = make_uint4(f2tf32(a0.x), f2tf32(a0.y), f2tf32(a0.z), f2tf32(a0.w));
        uint4 ua1 = make_uint4(f2tf32(a1.x), f2tf32(a1.y), f2tf32(a1.z), f2tf32(a1.w));
        uint4 ub0 = make_uint4(f2tf32(b0.x), f2tf32(b0.y), f2tf32(b0.z), f2tf32(b0.w));
        uint4 ub1 = make_uint4(f2tf32(b1.x), f2tf32(b1.y), f2tf32(b1.z), f2tf32(b1.w));
        *(uint4*)&As[0][lr][lc]     = ua0;
        *(uint4*)&As[0][lr][lc + 4] = ua1;
        *(uint4*)&Bs[0][lr][lc]     = ub0;
        *(uint4*)&Bs[0][lr][lc + 4] = ub1;
    }
    __syncthreads();

    for (int kt = 0; kt < nk; kt++) {
        const int cur = kt & 1;
        float4 pa0, pa1, pb0, pb1;
        const bool has_next = (kt + 1 < nk);
        if (has_next) {
            int k0 = (kt + 1) << 4;
            pa0 = *(const float4*)&A[(size_t)(m0 + lr) * Kdim + k0 + lc];
            pa1 = *(const float4*)&A[(size_t)(m0 + lr) * Kdim + k0 + lc + 4];
            pb0 = *(const float4*)&W[(size_t)(n0 + lr) * Kdim + k0 + lc];
            pb1 = *(const float4*)&W[(size_t)(n0 + lr) * Kdim + k0 + lc + 4];
        }

        #pragma unroll
        for (int ks = 0; ks < 16; ks += 8) {
            uint32_t af[4][4], bf[4][2];
            #pragma unroll
            for (int mt = 0; mt < 4; mt++) {
                int m = mw + mt * 16 + grp;
                af[mt][0] = As[cur][m][ks + qp];
                af[mt][1] = As[cur][m + 8][ks + qp];
                af[mt][2] = As[cur][m][ks + qp + 4];
                af[mt][3] = As[cur][m + 8][ks + qp + 4];
            }
            #pragma unroll
            for (int nt = 0; nt < 4; nt++) {
                int n = nw + nt * 8 + grp;
                bf[nt][0] = Bs[cur][n][ks + qp];
                bf[nt][1] = Bs[cur][n][ks + qp + 4];
            }
            #pragma unroll
            for (int mt = 0; mt < 4; mt++)
                #pragma unroll
                for (int nt = 0; nt < 4; nt++)
                    mma_tf32(acc[mt][nt], af[mt], bf[nt]);
        }

        if (has_next) {
            const int nxt = cur ^ 1;
            uint4 ua0 = make_uint4(f2tf32(pa0.x), f2tf32(pa0.y), f2tf32(pa0.z), f2tf32(pa0.w));
            uint4 ua1 = make_uint4(f2tf32(pa1.x), f2tf32(pa1.y), f2tf32(pa1.z), f2tf32(pa1.w));
            uint4 ub0 = make_uint4(f2tf32(pb0.x), f2tf32(pb0.y), f2tf32(pb0.z), f2tf32(pb0.w));
            uint4 ub1 = make_uint4(f2tf32(pb1.x), f2tf32(pb1.y), f2tf32(pb1.z), f2tf32(pb1.w));
            *(uint4*)&As[nxt][lr][lc]     = ua0;
            *(uint4*)&As[nxt][lr][lc + 4] = ua1;
            *(uint4*)&Bs[nxt][lr][lc]     = ub0;
            *(uint4*)&Bs[nxt][lr][lc + 4] = ub1;
            __syncthreads();
        }
    }

    // epilogue: bias + optional gelu, 2-float stores
    #pragma unroll
    for (int nt = 0; nt < 4; nt++) {
        int col = n0 + nw + nt * 8 + qp * 2;
        float b0 = bias[col], b1 = bias[col + 1];
        #pragma unroll
        for (int mt = 0; mt < 4; mt++) {
            int row0 = m0 + mw + mt * 16 + grp;
            float v0 = acc[mt][nt][0] + b0;
            float v1 = acc[mt][nt][1] + b1;
            float v2 = acc[mt][nt][2] + b0;
            float v3 = acc[mt][nt][3] + b1;
            if (ACT == 1) { v0 = gelu_exact(v0); v1 = gelu_exact(v1); v2 = gelu_exact(v2); v3 = gelu_exact(v3); }
            *(float2*)&C[(size_t)row0 * N + col]       = make_float2(v0, v1);
            *(float2*)&C[(size_t)(row0 + 8) * N + col] = make_float2(v2, v3);
        }
    }
}

// ---------------- split qkv (ROWS x 768) -> q/k/v in (B, NH, SEQ, DH) --------
__global__ void split_heads(const float* __restrict__ qkv,
                            float* __restrict__ q, float* __restrict__ k,
                            float* __restrict__ v)
{
    int idx = blockIdx.x * blockDim.x + threadIdx.x;
    if (idx >= ROWS*DM) return;
    int dh = idx & 31;
    int s  = (idx >> 5) & (SEQ - 1);
    int hh = (idx >> 16) & (NHD - 1);
    int b  = idx >> 19;
    int src = (s*BT + b) * (3*DM) + hh*DH + dh;
    q[idx] = qkv[src];
    k[idx] = qkv[src + DM];
    v[idx] = qkv[src + 2*DM];
}

// ---------------- merge heads (B, NH, SEQ, DH) -> (ROWS x DM) ----------------
__global__ void merge_heads(const float* __restrict__ att, float* __restrict__ out)
{
    int idx = blockIdx.x * blockDim.x + threadIdx.x;
    if (idx >= ROWS*DM) return;
    int d   = idx & (DM - 1);
    int row = idx >> 8;
    int s = row >> 2, b = row & 3;
    int hh = d >> 5, dh = d & 31;
    out[idx] = att[(((size_t)(b*NHD + hh))*SEQ + s)*DH + dh];
}

// ---------------- flash-style attention ---------------------------------------
__global__ __launch_bounds__(256)
void attn_kernel(const float* __restrict__ Q, const float* __restrict__ K,
                 const float* __restrict__ V, const int* __restrict__ sep,
                 float* __restrict__ O)
{
    const int b = blockIdx.z, h = blockIdx.y;
    const int q0 = blockIdx.x * 32;
    const size_t head_off = ((size_t)(b*NHD + h)) * SEQ * DH;
    const float* qb = Q + head_off;
    const float* kb = K + head_off;
    const float* vb = V + head_off;
    float*       ob = O + head_off;

    __shared__ float Qs[32][32];
    __shared__ float Ks[32][32];
    __shared__ float Vs[32][32];
    __shared__ float S [32][33];
    __shared__ float m_s[32], l_s[32], a_s[32];

    const int tid = threadIdx.x;
    {
        int e = tid * 4, r = e >> 5, dd = e & 31;
        *(float4*)&Qs[r][dd] = *(const float4*)&qb[(size_t)(q0 + r)*DH + dd];
    }
    if (tid < 32) { m_s[tid] = -1e30f; l_s[tid] = 0.f; }

    float acc0 = 0.f, acc1 = 0.f, acc2 = 0.f, acc3 = 0.f;
    const int qi = tid >> 3;
    const int c0 = (tid & 7) * 4;
    const int M_ = *sep;
    const int nch = (M_ + 31) >> 5;
    const float scale = 0.17677669529663687f;

    for (int c = 0; c <= nch; c++) {
        const bool diag = (c == nch);
        const int kbase = diag ? q0 : c * 32;
        __syncthreads();
        {
            int e = tid * 4, r = e >> 5, dd = e & 31;
            int key = kbase + r;
            float4 kv, vv;
            if (!diag && key >= M_) {
                kv = make_float4(0,0,0,0); vv = kv;
            } else {
                kv = *(const float4*)&kb[(size_t)key*DH + dd];
                vv = *(const float4*)&vb[(size_t)key*DH + dd];
            }
            *(float4*)&Ks[r][dd] = kv;
            *(float4*)&Vs[r][dd] = vv;
        }
        __syncthreads();

        #pragma unroll
        for (int u = 0; u < 4; u++) {
            int kj = c0 + u;
            int key = kbase + kj;
            bool ok = diag ? (key >= M_ && kj == qi) : (key < M_);
            float sv = -1e30f;
            if (ok) {
                float dot = 0.f;
                const float4* qr = (const float4*)Qs[qi];
                const float4* kr = (const float4*)Ks[kj];
                #pragma unroll
                for (int d4 = 0; d4 < 8; d4++) {
                    float4 a = qr[d4], bb = kr[d4];
                    dot += a.x*bb.x + a.y*bb.y + a.z*bb.z + a.w*bb.w;
                }
                sv = dot * scale;
            }
            S[qi][kj] = sv;
        }
        __syncthreads();

        if (tid < 32) {
            float mold = m_s[tid];
            float mx = mold;
            #pragma unroll
            for (int j = 0; j < 32; j++) mx = fmaxf(mx, S[tid][j]);
            if (mx <= -1e29f) {
                a_s[tid] = 1.f;
                #pragma unroll
                for (int j = 0; j < 32; j++) S[tid][j] = 0.f;
            } else {
                float al = expf(mold - mx);
                float ls = 0.f;
                #pragma unroll
                for (int j = 0; j < 32; j++) {
                    float p = expf(S[tid][j] - mx);
                    S[tid][j] = p;
                    ls += p;
                }
                m_s[tid] = mx;
                l_s[tid] = l_s[tid] * al + ls;
                a_s[tid] = al;
            }
        }
        __syncthreads();

        float al = a_s[qi];
        acc0 *= al; acc1 *= al; acc2 *= al; acc3 *= al;
        #pragma unroll
        for (int kj2 = 0; kj2 < 32; kj2++) {
            float p = S[qi][kj2];
            acc0 += p * Vs[kj2][c0 + 0];
            acc1 += p * Vs[kj2][c0 + 1];
            acc2 += p * Vs[kj2][c0 + 2];
            acc3 += p * Vs[kj2][c0 + 3];
        }
    }

    float inv = 1.f / l_s[qi];
    float4 r4 = make_float4(acc0*inv, acc1*inv, acc2*inv, acc3*inv);
    *(float4*)&ob[(size_t)(q0 + qi)*DH + c0] = r4;
}

// ---------------- residual add + layer norm ----------------------------------
__global__ void add_ln_kernel(const float* __restrict__ resid,
                              const float* __restrict__ delta,
                              const float* __restrict__ g, const float* __restrict__ bb,
                              float* __restrict__ out)
{
    int row = blockIdx.x;
    int d = threadIdx.x;
    __shared__ float red[DM];
    __shared__ float mu_s, rstd_s;
    float v = resid[(size_t)row*DM + d] + delta[(size_t)row*DM + d];
    red[d] = v;
    __syncthreads();
    for (int off = 128; off > 0; off >>= 1) {
        if (d < off) red[d] += red[d + off];
        __syncthreads();
    }
    if (d == 0) mu_s = red[0] * (1.0f / DM);
    __syncthreads();
    float mu = mu_s;
    float c = v - mu;
    red[d] = c * c;
    __syncthreads();
    for (int off = 128; off > 0; off >>= 1) {
        if (d < off) red[d] += red[d + off];
        __syncthreads();
    }
    if (d == 0) rstd_s = rsqrtf(red[0] * (1.0f / DM) + 1e-5f);
    __syncthreads();
    out[(size_t)row*DM + d] = c * rstd_s * g[d] + bb[d];
}

// ---------------- final head: out[(s-M)*B+b] = hid . w2 + b2 -----------------
__global__ void head2_kernel(const float* __restrict__ hid, const float* __restrict__ w2,
                             const float* __restrict__ b2, const int* __restrict__ sep,
                             float* __restrict__ out)
{
    int row = blockIdx.x;
    int M_ = *sep;
    int s = row >> 2, b = row & 3;
    if (s < M_) return;
    float sum = 0.f;
    for (int t = threadIdx.x; t < DFF; t += 128)
        sum += hid[(size_t)row*DFF + t] * w2[t];
    for (int off = 16; off > 0; off >>= 1)
        sum += __shfl_down_sync(0xffffffffu, sum, off);
    __shared__ float ws[4];
    if ((threadIdx.x & 31) == 0) ws[threadIdx.x >> 5] = sum;
    __syncthreads();
    if (threadIdx.x == 0)
        out[(s - M_)*BT + b] = ws[0] + ws[1] + ws[2] + ws[3] + b2[0];
}

// =============================================================================
extern "C" void kernel_launch(void* const* d_in, const int* in_sizes, int n_in,
                              void* d_out, int out_size)
{
    (void)in_sizes; (void)n_in; (void)out_size;
    const float* x        = (const float*)d_in[0];
    const float* y        = (const float*)d_in[1];
    const int*   sep      = (const int*  )d_in[2];
    const float* xenc_w   = (const float*)d_in[3];
    const float* xenc_b   = (const float*)d_in[4];
    const float* yenc_w   = (const float*)d_in[5];
    const float* yenc_b   = (const float*)d_in[6];
    const float* in_proj_w= (const float*)d_in[7];
    const float* in_proj_b= (const float*)d_in[8];
    const float* out_proj_w=(const float*)d_in[9];
    const float* out_proj_b=(const float*)d_in[10];
    const float* ln1_g    = (const float*)d_in[11];
    const float* ln1_b    = (const float*)d_in[12];
    const float* lin1_w   = (const float*)d_in[13];
    const float* lin1_b   = (const float*)d_in[14];
    const float* lin2_w   = (const float*)d_in[15];
    const float* lin2_b   = (const float*)d_in[16];
    const float* ln2_g    = (const float*)d_in[17];
    const float* ln2_b    = (const float*)d_in[18];
    const float* head_w1  = (const float*)d_in[19];
    const float* head_b1  = (const float*)d_in[20];
    const float* head_w2  = (const float*)d_in[21];
    const float* head_b2  = (const float*)d_in[22];
    float* out = (float*)d_out;

    float *h, *qkv, *q, *k, *v, *att, *tmp, *tmp2, *ff;
    cudaGetSymbolAddress((void**)&h,    g_h);
    cudaGetSymbolAddress((void**)&qkv,  g_qkv);
    cudaGetSymbolAddress((void**)&q,    g_q);
    cudaGetSymbolAddress((void**)&k,    g_k);
    cudaGetSymbolAddress((void**)&v,    g_v);
    cudaGetSymbolAddress((void**)&att,  g_att);
    cudaGetSymbolAddress((void**)&tmp,  g_tmp);
    cudaGetSymbolAddress((void**)&tmp2, g_tmp2);
    cudaGetSymbolAddress((void**)&ff,   g_ff);

    embed_kernel<<<ROWS, DM>>>(x, y, sep, xenc_w, xenc_b, yenc_w, yenc_b, h);

    const int elem_grid = (ROWS*DM + 255) / 256;

    for (int l = 0; l < NL; l++) {
        gemm_tc<0><<<dim3(3*DM/128, ROWS/128), 256>>>(
            h, in_proj_w + (size_t)l*3*DM*DM, in_proj_b + (size_t)l*3*DM, qkv, 3*DM, DM, nullptr);
        split_heads<<<elem_grid, 256>>>(qkv, q, k, v);
        attn_kernel<<<dim3(SEQ/32, NHD, BT), 256>>>(q, k, v, sep, att);
        merge_heads<<<elem_grid, 256>>>(att, tmp);
        gemm_tc<0><<<dim3(DM/128, ROWS/128), 256>>>(
            tmp, out_proj_w + (size_t)l*DM*DM, out_proj_b + (size_t)l*DM, tmp2, DM, DM, nullptr);
        add_ln_kernel<<<ROWS, DM>>>(h, tmp2, ln1_g + (size_t)l*DM, ln1_b + (size_t)l*DM, h);
        gemm_tc<1><<<dim3(DFF/128, ROWS/128), 256>>>(
            h, lin1_w + (size_t)l*DFF*DM, lin1_b + (size_t)l*DFF, ff, DFF, DM, nullptr);
        gemm_tc<0><<<dim3(DM/128, ROWS/128), 256>>>(
            ff, lin2_w + (size_t)l*DM*DFF, lin2_b + (size_t)l*DM, tmp2, DM, DFF, nullptr);
        add_ln_kernel<<<ROWS, DM>>>(h, tmp2, ln2_g + (size_t)l*DM, ln2_b + (size_t)l*DM, h);
    }

    gemm_tc<1><<<dim3(DFF/128, ROWS/128), 256>>>(h, head_w1, head_b1, ff, DFF, DM, sep);
    head2_kernel<<<ROWS, 128>>>(ff, head_w2, head_b2, sep, out);
}

// round 4
// speedup vs baseline: 1.0691x; 1.0005x over previous
#include <cuda_runtime.h>
#include <cstdint>
#include <math.h>

#define SEQ  2048
#define BT   4
#define XD   16
#define DM   256
#define NHD  8
#define DH   32
#define DFF  512
#define NL   2
#define ROWS (SEQ*BT)

// ---------------- scratch (static device globals; no allocation) -------------
__device__ float g_h   [ROWS*DM];
__device__ float g_qkv [ROWS*3*DM];
__device__ float g_q   [ROWS*DM];
__device__ float g_k   [ROWS*DM];
__device__ float g_v   [ROWS*DM];
__device__ float g_att [ROWS*DM];
__device__ float g_tmp [ROWS*DM];
__device__ float g_tmp2[ROWS*DM];
__device__ float g_ff  [ROWS*DFF];

// ---------------- embed: tokens = xenc(x) (+ yenc(y) for s < M) --------------
__global__ void embed_kernel(const float* __restrict__ x, const float* __restrict__ y,
                             const int* __restrict__ sep,
                             const float* __restrict__ xw, const float* __restrict__ xb,
                             const float* __restrict__ yw, const float* __restrict__ yb,
                             float* __restrict__ h)
{
    int row = blockIdx.x;           // s*BT + b
    int s = row >> 2, b = row & 3;
    int d = threadIdx.x;            // 0..255
    __shared__ float xs[XD];
    if (threadIdx.x < XD) xs[threadIdx.x] = x[(s*BT + b)*XD + threadIdx.x];
    __syncthreads();
    float acc = xb[d];
    #pragma unroll
    for (int j = 0; j < XD; j++) acc += xs[j] * xw[d*XD + j];
    int M_ = *sep;
    if (s < M_) acc += y[s*BT + b] * yw[d] + yb[d];
    h[row*DM + d] = acc;
}

// ---------------- helpers -----------------------------------------------------
__device__ __forceinline__ float gelu_exact(float v) {
    return 0.5f * v * (1.0f + erff(v * 0.70710678118654752f));
}
__device__ __forceinline__ uint32_t f2tf32(float f) {
    uint32_t r;
    asm("cvt.rna.tf32.f32 %0, %1;" : "=r"(r) : "f"(f));
    return r;
}
__device__ __forceinline__ void mma_tf32(float c[4], const uint32_t a[4], const uint32_t b[2]) {
    asm volatile(
        "mma.sync.aligned.m16n8k8.row.col.f32.tf32.tf32.f32 "
        "{%0,%1,%2,%3}, {%4,%5,%6,%7}, {%8,%9}, {%0,%1,%2,%3};\n"
        : "+f"(c[0]), "+f"(c[1]), "+f"(c[2]), "+f"(c[3])
        : "r"(a[0]), "r"(a[1]), "r"(a[2]), "r"(a[3]), "r"(b[0]), "r"(b[1]));
}

// ---------------- TF32 tensor-core GEMM: C = A (Mr x K) * W^T (N x K) + bias --
// block tile 128x128, BK=16, double-buffered smem, 8 warps of 64x32 warp tiles.
template<int ACT>   // 0 = none, 1 = exact gelu
__global__ __launch_bounds__(256)
void gemm_tc(const float* __restrict__ A, const float* __restrict__ W,
             const float* __restrict__ bias, float* __restrict__ C,
             int N, int Kdim, const int* __restrict__ sep_skip)
{
    const int m0 = blockIdx.y * 128;
    const int n0 = blockIdx.x * 128;
    if (sep_skip) {                               // head GEMM: skip blocks fully below M
        int M_ = *sep_skip;
        if (((m0 + 127) >> 2) < M_) return;
    }

    __shared__ uint32_t As[2][128][20];           // m-major, stride 20 (conflict-free frags)
    __shared__ uint32_t Bs[2][128][20];           // n-major, stride 20

    const int tid  = threadIdx.x;
    const int lane = tid & 31;
    const int warp = tid >> 5;
    const int grp  = lane >> 2;                   // 0..7
    const int qp   = lane & 3;                    // 0..3
    const int mw   = (warp >> 2) * 64;            // warp m offset (0 or 64)
    const int nw   = (warp & 3) * 32;             // warp n offset (0..96)

    // gmem load mapping: each thread loads 2 float4 for A and 2 for B per k-tile
    const int lr = tid >> 1;                      // 0..127 (row within tile)
    const int lc = (tid & 1) * 8;                 // 0 or 8 (k offset)

    float acc[4][4][4];
    #pragma unroll
    for (int mt = 0; mt < 4; mt++)
        #pragma unroll
        for (int nt = 0; nt < 4; nt++)
            #pragma unroll
            for (int e = 0; e < 4; e++) acc[mt][nt][e] = 0.f;

    const int nk = Kdim >> 4;

    // initial tile -> buf 0
    {
        float4 a0 = *(const float4*)&A[(size_t)(m0 + lr) * Kdim + lc];
        float4 a1 = *(const float4*)&A[(size_t)(m0 + lr) * Kdim + lc + 4];
        float4 b0 = *(const float4*)&W[(size_t)(n0 + lr) * Kdim + lc];
        float4 b1 = *(const float4*)&W[(size_t)(n0 + lr) * Kdim + lc + 4];
        uint4 ua0 = make_uint4(f2tf32(a0.x), f2tf32(a0.y), f2tf32(a0.z), f2tf32(a0.w));
        uint4 ua1 = make_uint4(f2tf32(a1.x), f2tf32(a1.y), f2tf32(a1.z), f2tf32(a1.w));
        uint4 ub0 = make_uint4(f2tf32(b0.x), f2tf32(b0.y), f2tf32(b0.z), f2tf32(b0.w));
        uint4 ub1 = make_uint4(f2tf32(b1.x), f2tf32(b1.y), f2tf32(b1.z), f2tf32(b1.w));
        *(uint4*)&As[0][lr][lc]     = ua0;
        *(uint4*)&As[0][lr][lc + 4] = ua1;
        *(uint4*)&Bs[0][lr][lc]     = ub0;
        *(uint4*)&Bs[0][lr][lc + 4] = ub1;
    }
    __syncthreads();

    for (int kt = 0; kt < nk; kt++) {
        const int cur = kt & 1;
        float4 pa0, pa1, pb0, pb1;
        const bool has_next = (kt + 1 < nk);
        if (has_next) {
            int k0 = (kt + 1) << 4;
            pa0 = *(const float4*)&A[(size_t)(m0 + lr) * Kdim + k0 + lc];
            pa1 = *(const float4*)&A[(size_t)(m0 + lr) * Kdim + k0 + lc + 4];
            pb0 = *(const float4*)&W[(size_t)(n0 + lr) * Kdim + k0 + lc];
            pb1 = *(const float4*)&W[(size_t)(n0 + lr) * Kdim + k0 + lc + 4];
        }

        #pragma unroll
        for (int ks = 0; ks < 16; ks += 8) {
            uint32_t af[4][4], bf[4][2];
            #pragma unroll
            for (int mt = 0; mt < 4; mt++) {
                int m = mw + mt * 16 + grp;
                af[mt][0] = As[cur][m][ks + qp];
                af[mt][1] = As[cur][m + 8][ks + qp];
                af[mt][2] = As[cur][m][ks + qp + 4];
                af[mt][3] = As[cur][m + 8][ks + qp + 4];
            }
            #pragma unroll
            for (int nt = 0; nt < 4; nt++) {
                int n = nw + nt * 8 + grp;
                bf[nt][0] = Bs[cur][n][ks + qp];
                bf[nt][1] = Bs[cur][n][ks + qp + 4];
            }
            #pragma unroll
            for (int mt = 0; mt < 4; mt++)
                #pragma unroll
                for (int nt = 0; nt < 4; nt++)
                    mma_tf32(acc[mt][nt], af[mt], bf[nt]);
        }

        if (has_next) {
            const int nxt = cur ^ 1;
            uint4 ua0 = make_uint4(f2tf32(pa0.x), f2tf32(pa0.y), f2tf32(pa0.z), f2tf32(pa0.w));
            uint4 ua1 = make_uint4(f2tf32(pa1.x), f2tf32(pa1.y), f2tf32(pa1.z), f2tf32(pa1.w));
            uint4 ub0 = make_uint4(f2tf32(pb0.x), f2tf32(pb0.y), f2tf32(pb0.z), f2tf32(pb0.w));
            uint4 ub1 = make_uint4(f2tf32(pb1.x), f2tf32(pb1.y), f2tf32(pb1.z), f2tf32(pb1.w));
            *(uint4*)&As[nxt][lr][lc]     = ua0;
            *(uint4*)&As[nxt][lr][lc + 4] = ua1;
            *(uint4*)&Bs[nxt][lr][lc]     = ub0;
            *(uint4*)&Bs[nxt][lr][lc + 4] = ub1;
            __syncthreads();
        }
    }

    // epilogue: bias + optional gelu, 2-float stores
    #pragma unroll
    for (int nt = 0; nt < 4; nt++) {
        int col = n0 + nw + nt * 8 + qp * 2;
        float b0 = bias[col], b1 = bias[col + 1];
        #pragma unroll
        for (int mt = 0; mt < 4; mt++) {
            int row0 = m0 + mw + mt * 16 + grp;
            float v0 = acc[mt][nt][0] + b0;
            float v1 = acc[mt][nt][1] + b1;
            float v2 = acc[mt][nt][2] + b0;
            float v3 = acc[mt][nt][3] + b1;
            if (ACT == 1) { v0 = gelu_exact(v0); v1 = gelu_exact(v1); v2 = gelu_exact(v2); v3 = gelu_exact(v3); }
            *(float2*)&C[(size_t)row0 * N + col]       = make_float2(v0, v1);
            *(float2*)&C[(size_t)(row0 + 8) * N + col] = make_float2(v2, v3);
        }
    }
}

// ---------------- split qkv (ROWS x 768) -> q/k/v in (B, NH, SEQ, DH) --------
__global__ void split_heads(const float* __restrict__ qkv,
                            float* __restrict__ q, float* __restrict__ k,
                            float* __restrict__ v)
{
    int idx = blockIdx.x * blockDim.x + threadIdx.x;
    if (idx >= ROWS*DM) return;
    int dh = idx & 31;
    int s  = (idx >> 5) & (SEQ - 1);
    int hh = (idx >> 16) & (NHD - 1);
    int b  = idx >> 19;
    int src = (s*BT + b) * (3*DM) + hh*DH + dh;
    q[idx] = qkv[src];
    k[idx] = qkv[src + DM];
    v[idx] = qkv[src + 2*DM];
}

// ---------------- merge heads (B, NH, SEQ, DH) -> (ROWS x DM) ----------------
__global__ void merge_heads(const float* __restrict__ att, float* __restrict__ out)
{
    int idx = blockIdx.x * blockDim.x + threadIdx.x;
    if (idx >= ROWS*DM) return;
    int d   = idx & (DM - 1);
    int row = idx >> 8;
    int s = row >> 2, b = row & 3;
    int hh = d >> 5, dh = d & 31;
    out[idx] = att[(((size_t)(b*NHD + hh))*SEQ + s)*DH + dh];
}

// ---------------- flash-style attention ---------------------------------------
__global__ __launch_bounds__(256)
void attn_kernel(const float* __restrict__ Q, const float* __restrict__ K,
                 const float* __restrict__ V, const int* __restrict__ sep,
                 float* __restrict__ O)
{
    const int b = blockIdx.z, h = blockIdx.y;
    const int q0 = blockIdx.x * 32;
    const size_t head_off = ((size_t)(b*NHD + h)) * SEQ * DH;
    const float* qb = Q + head_off;
    const float* kb = K + head_off;
    const float* vb = V + head_off;
    float*       ob = O + head_off;

    __shared__ float Qs[32][32];
    __shared__ float Ks[32][32];
    __shared__ float Vs[32][32];
    __shared__ float S [32][33];
    __shared__ float m_s[32], l_s[32], a_s[32];

    const int tid = threadIdx.x;
    {
        int e = tid * 4, r = e >> 5, dd = e & 31;
        *(float4*)&Qs[r][dd] = *(const float4*)&qb[(size_t)(q0 + r)*DH + dd];
    }
    if (tid < 32) { m_s[tid] = -1e30f; l_s[tid] = 0.f; }

    float acc0 = 0.f, acc1 = 0.f, acc2 = 0.f, acc3 = 0.f;
    const int qi = tid >> 3;
    const int c0 = (tid & 7) * 4;
    const int M_ = *sep;
    const int nch = (M_ + 31) >> 5;
    const float scale = 0.17677669529663687f;

    for (int c = 0; c <= nch; c++) {
        const bool diag = (c == nch);
        const int kbase = diag ? q0 : c * 32;
        __syncthreads();
        {
            int e = tid * 4, r = e >> 5, dd = e & 31;
            int key = kbase + r;
            float4 kv, vv;
            if (!diag && key >= M_) {
                kv = make_float4(0,0,0,0); vv = kv;
            } else {
                kv = *(const float4*)&kb[(size_t)key*DH + dd];
                vv = *(const float4*)&vb[(size_t)key*DH + dd];
            }
            *(float4*)&Ks[r][dd] = kv;
            *(float4*)&Vs[r][dd] = vv;
        }
        __syncthreads();

        #pragma unroll
        for (int u = 0; u < 4; u++) {
            int kj = c0 + u;
            int key = kbase + kj;
            bool ok = diag ? (key >= M_ && kj == qi) : (key < M_);
            float sv = -1e30f;
            if (ok) {
                float dot = 0.f;
                const float4* qr = (const float4*)Qs[qi];
                const float4* kr = (const float4*)Ks[kj];
                #pragma unroll
                for (int d4 = 0; d4 < 8; d4++) {
                    float4 a = qr[d4], bb = kr[d4];
                    dot += a.x*bb.x + a.y*bb.y + a.z*bb.z + a.w*bb.w;
                }
                sv = dot * scale;
            }
            S[qi][kj] = sv;
        }
        __syncthreads();

        if (tid < 32) {
            float mold = m_s[tid];
            float mx = mold;
            #pragma unroll
            for (int j = 0; j < 32; j++) mx = fmaxf(mx, S[tid][j]);
            if (mx <= -1e29f) {
                a_s[tid] = 1.f;
                #pragma unroll
                for (int j = 0; j < 32; j++) S[tid][j] = 0.f;
            } else {
                float al = expf(mold - mx);
                float ls = 0.f;
                #pragma unroll
                for (int j = 0; j < 32; j++) {
                    float p = expf(S[tid][j] - mx);
                    S[tid][j] = p;
                    ls += p;
                }
                m_s[tid] = mx;
                l_s[tid] = l_s[tid] * al + ls;
                a_s[tid] = al;
            }
        }
        __syncthreads();

        float al = a_s[qi];
        acc0 *= al; acc1 *= al; acc2 *= al; acc3 *= al;
        #pragma unroll
        for (int kj2 = 0; kj2 < 32; kj2++) {
            float p = S[qi][kj2];
            acc0 += p * Vs[kj2][c0 + 0];
            acc1 += p * Vs[kj2][c0 + 1];
            acc2 += p * Vs[kj2][c0 + 2];
            acc3 += p * Vs[kj2][c0 + 3];
        }
    }

    float inv = 1.f / l_s[qi];
    float4 r4 = make_float4(acc0*inv, acc1*inv, acc2*inv, acc3*inv);
    *(float4*)&ob[(size_t)(q0 + qi)*DH + c0] = r4;
}

// ---------------- residual add + layer norm ----------------------------------
__global__ void add_ln_kernel(const float* __restrict__ resid,
                              const float* __restrict__ delta,
                              const float* __restrict__ g, const float* __restrict__ bb,
                              float* __restrict__ out)
{
    int row = blockIdx.x;
    int d = threadIdx.x;
    __shared__ float red[DM];
    __shared__ float mu_s, rstd_s;
    float v = resid[(size_t)row*DM + d] + delta[(size_t)row*DM + d];
    red[d] = v;
    __syncthreads();
    for (int off = 128; off > 0; off >>= 1) {
        if (d < off) red[d] += red[d + off];
        __syncthreads();
    }
    if (d == 0) mu_s = red[0] * (1.0f / DM);
    __syncthreads();
    float mu = mu_s;
    float c = v - mu;
    red[d] = c * c;
    __syncthreads();
    for (int off = 128; off > 0; off >>= 1) {
        if (d < off) red[d] += red[d + off];
        __syncthreads();
    }
    if (d == 0) rstd_s = rsqrtf(red[0] * (1.0f / DM) + 1e-5f);
    __syncthreads();
    out[(size_t)row*DM + d] = c * rstd_s * g[d] + bb[d];
}

// ---------------- final head: out[(s-M)*B+b] = hid . w2 + b2 -----------------
__global__ void head2_kernel(const float* __restrict__ hid, const float* __restrict__ w2,
                             const float* __restrict__ b2, const int* __restrict__ sep,
                             float* __restrict__ out)
{
    int row = blockIdx.x;
    int M_ = *sep;
    int s = row >> 2, b = row & 3;
    if (s < M_) return;
    float sum = 0.f;
    for (int t = threadIdx.x; t < DFF; t += 128)
        sum += hid[(size_t)row*DFF + t] * w2[t];
    for (int off = 16; off > 0; off >>= 1)
        sum += __shfl_down_sync(0xffffffffu, sum, off);
    __shared__ float ws[4];
    if ((threadIdx.x & 31) == 0) ws[threadIdx.x >> 5] = sum;
    __syncthreads();
    if (threadIdx.x == 0)
        out[(s - M_)*BT + b] = ws[0] + ws[1] + ws[2] + ws[3] + b2[0];
}

// =============================================================================
extern "C" void kernel_launch(void* const* d_in, const int* in_sizes, int n_in,
                              void* d_out, int out_size)
{
    (void)in_sizes; (void)n_in; (void)out_size;
    const float* x        = (const float*)d_in[0];
    const float* y        = (const float*)d_in[1];
    const int*   sep      = (const int*  )d_in[2];
    const float* xenc_w   = (const float*)d_in[3];
    const float* xenc_b   = (const float*)d_in[4];
    const float* yenc_w   = (const float*)d_in[5];
    const float* yenc_b   = (const float*)d_in[6];
    const float* in_proj_w= (const float*)d_in[7];
    const float* in_proj_b= (const float*)d_in[8];
    const float* out_proj_w=(const float*)d_in[9];
    const float* out_proj_b=(const float*)d_in[10];
    const float* ln1_g    = (const float*)d_in[11];
    const float* ln1_b    = (const float*)d_in[12];
    const float* lin1_w   = (const float*)d_in[13];
    const float* lin1_b   = (const float*)d_in[14];
    const float* lin2_w   = (const float*)d_in[15];
    const float* lin2_b   = (const float*)d_in[16];
    const float* ln2_g    = (const float*)d_in[17];
    const float* ln2_b    = (const float*)d_in[18];
    const float* head_w1  = (const float*)d_in[19];
    const float* head_b1  = (const float*)d_in[20];
    const float* head_w2  = (const float*)d_in[21];
    const float* head_b2  = (const float*)d_in[22];
    float* out = (float*)d_out;

    float *h, *qkv, *q, *k, *v, *att, *tmp, *tmp2, *ff;
    cudaGetSymbolAddress((void**)&h,    g_h);
    cudaGetSymbolAddress((void**)&qkv,  g_qkv);
    cudaGetSymbolAddress((void**)&q,    g_q);
    cudaGetSymbolAddress((void**)&k,    g_k);
    cudaGetSymbolAddress((void**)&v,    g_v);
    cudaGetSymbolAddress((void**)&att,  g_att);
    cudaGetSymbolAddress((void**)&tmp,  g_tmp);
    cudaGetSymbolAddress((void**)&tmp2, g_tmp2);
    cudaGetSymbolAddress((void**)&ff,   g_ff);

    embed_kernel<<<ROWS, DM>>>(x, y, sep, xenc_w, xenc_b, yenc_w, yenc_b, h);

    const int elem_grid = (ROWS*DM + 255) / 256;

    for (int l = 0; l < NL; l++) {
        gemm_tc<0><<<dim3(3*DM/128, ROWS/128), 256>>>(
            h, in_proj_w + (size_t)l*3*DM*DM, in_proj_b + (size_t)l*3*DM, qkv, 3*DM, DM, nullptr);
        split_heads<<<elem_grid, 256>>>(qkv, q, k, v);
        attn_kernel<<<dim3(SEQ/32, NHD, BT), 256>>>(q, k, v, sep, att);
        merge_heads<<<elem_grid, 256>>>(att, tmp);
        gemm_tc<0><<<dim3(DM/128, ROWS/128), 256>>>(
            tmp, out_proj_w + (size_t)l*DM*DM, out_proj_b + (size_t)l*DM, tmp2, DM, DM, nullptr);
        add_ln_kernel<<<ROWS, DM>>>(h, tmp2, ln1_g + (size_t)l*DM, ln1_b + (size_t)l*DM, h);
        gemm_tc<1><<<dim3(DFF/128, ROWS/128), 256>>>(
            h, lin1_w + (size_t)l*DFF*DM, lin1_b + (size_t)l*DFF, ff, DFF, DM, nullptr);
        gemm_tc<0><<<dim3(DM/128, ROWS/128), 256>>>(
            ff, lin2_w + (size_t)l*DM*DFF, lin2_b + (size_t)l*DM, tmp2, DM, DFF, nullptr);
        add_ln_kernel<<<ROWS, DM>>>(h, tmp2, ln2_g + (size_t)l*DM, ln2_b + (size_t)l*DM, h);
    }

    gemm_tc<1><<<dim3(DFF/128, ROWS/128), 256>>>(h, head_w1, head_b1, ff, DFF, DM, sep);
    head2_kernel<<<ROWS, 128>>>(ff, head_w2, head_b2, sep, out);
}

// round 5
// speedup vs baseline: 8.7690x; 8.2025x over previous
#include <cuda_runtime.h>
#include <cstdint>
#include <math.h>

#define SEQ  2048
#define BT   4
#define XD   16
#define DM   256
#define NHD  8
#define DH   32
#define DFF  512
#define NL   2
#define ROWS (SEQ*BT)

// ---------------- scratch (static device globals; no allocation) -------------
__device__ float g_h   [ROWS*DM];
__device__ float g_qkv [ROWS*3*DM];
__device__ float g_tmp [ROWS*DM];
__device__ float g_tmp2[ROWS*DM];
__device__ float g_ff  [ROWS*DFF];

// ---------------- embed: tokens = xenc(x) (+ yenc(y) for s < M) --------------
__global__ void embed_kernel(const float* __restrict__ x, const float* __restrict__ y,
                             const int* __restrict__ sep,
                             const float* __restrict__ xw, const float* __restrict__ xb,
                             const float* __restrict__ yw, const float* __restrict__ yb,
                             float* __restrict__ h)
{
    int row = blockIdx.x;           // s*BT + b
    int s = row >> 2, b = row & 3;
    int d = threadIdx.x;            // 0..255
    __shared__ float xs[XD];
    if (threadIdx.x < XD) xs[threadIdx.x] = x[(s*BT + b)*XD + threadIdx.x];
    __syncthreads();
    float acc = xb[d];
    #pragma unroll
    for (int j = 0; j < XD; j++) acc += xs[j] * xw[d*XD + j];
    int M_ = *sep;
    if (s < M_) acc += y[s*BT + b] * yw[d] + yb[d];
    h[row*DM + d] = acc;
}

// ---------------- helpers -----------------------------------------------------
__device__ __forceinline__ float gelu_exact(float v) {
    return 0.5f * v * (1.0f + erff(v * 0.70710678118654752f));
}
__device__ __forceinline__ uint32_t f2tf32(float f) {
    uint32_t r;
    asm("cvt.rna.tf32.f32 %0, %1;" : "=r"(r) : "f"(f));
    return r;
}
__device__ __forceinline__ void mma_tf32(float c[4], const uint32_t a[4], const uint32_t b[2]) {
    asm volatile(
        "mma.sync.aligned.m16n8k8.row.col.f32.tf32.tf32.f32 "
        "{%0,%1,%2,%3}, {%4,%5,%6,%7}, {%8,%9}, {%0,%1,%2,%3};\n"
        : "+f"(c[0]), "+f"(c[1]), "+f"(c[2]), "+f"(c[3])
        : "r"(a[0]), "r"(a[1]), "r"(a[2]), "r"(a[3]), "r"(b[0]), "r"(b[1]));
}

// ---------------- TF32 tensor-core GEMM: C = A (Mr x K) * W^T (N x K) + bias --
template<int ACT>   // 0 = none, 1 = exact gelu
__global__ __launch_bounds__(256)
void gemm_tc(const float* __restrict__ A, const float* __restrict__ W,
             const float* __restrict__ bias, float* __restrict__ C,
             int N, int Kdim, const int* __restrict__ sep_skip)
{
    const int m0 = blockIdx.y * 128;
    const int n0 = blockIdx.x * 128;
    if (sep_skip) {
        int M_ = *sep_skip;
        if (((m0 + 127) >> 2) < M_) return;
    }

    __shared__ uint32_t As[2][128][20];
    __shared__ uint32_t Bs[2][128][20];

    const int tid  = threadIdx.x;
    const int lane = tid & 31;
    const int warp = tid >> 5;
    const int grp  = lane >> 2;
    const int qp   = lane & 3;
    const int mw   = (warp >> 2) * 64;
    const int nw   = (warp & 3) * 32;

    const int lr = tid >> 1;
    const int lc = (tid & 1) * 8;

    float acc[4][4][4];
    #pragma unroll
    for (int mt = 0; mt < 4; mt++)
        #pragma unroll
        for (int nt = 0; nt < 4; nt++)
            #pragma unroll
            for (int e = 0; e < 4; e++) acc[mt][nt][e] = 0.f;

    const int nk = Kdim >> 4;

    {
        float4 a0 = *(const float4*)&A[(size_t)(m0 + lr) * Kdim + lc];
        float4 a1 = *(const float4*)&A[(size_t)(m0 + lr) * Kdim + lc + 4];
        float4 b0 = *(const float4*)&W[(size_t)(n0 + lr) * Kdim + lc];
        float4 b1 = *(const float4*)&W[(size_t)(n0 + lr) * Kdim + lc + 4];
        uint4 ua0 = make_uint4(f2tf32(a0.x), f2tf32(a0.y), f2tf32(a0.z), f2tf32(a0.w));
        uint4 ua1 = make_uint4(f2tf32(a1.x), f2tf32(a1.y), f2tf32(a1.z), f2tf32(a1.w));
        uint4 ub0 = make_uint4(f2tf32(b0.x), f2tf32(b0.y), f2tf32(b0.z), f2tf32(b0.w));
        uint4 ub1 = make_uint4(f2tf32(b1.x), f2tf32(b1.y), f2tf32(b1.z), f2tf32(b1.w));
        *(uint4*)&As[0][lr][lc]     = ua0;
        *(uint4*)&As[0][lr][lc + 4] = ua1;
        *(uint4*)&Bs[0][lr][lc]     = ub0;
        *(uint4*)&Bs[0][lr][lc + 4] = ub1;
    }
    __syncthreads();

    for (int kt = 0; kt < nk; kt++) {
        const int cur = kt & 1;
        float4 pa0, pa1, pb0, pb1;
        const bool has_next = (kt + 1 < nk);
        if (has_next) {
            int k0 = (kt + 1) << 4;
            pa0 = *(const float4*)&A[(size_t)(m0 + lr) * Kdim + k0 + lc];
            pa1 = *(const float4*)&A[(size_t)(m0 + lr) * Kdim + k0 + lc + 4];
            pb0 = *(const float4*)&W[(size_t)(n0 + lr) * Kdim + k0 + lc];
            pb1 = *(const float4*)&W[(size_t)(n0 + lr) * Kdim + k0 + lc + 4];
        }

        #pragma unroll
        for (int ks = 0; ks < 16; ks += 8) {
            uint32_t af[4][4], bf[4][2];
            #pragma unroll
            for (int mt = 0; mt < 4; mt++) {
                int m = mw + mt * 16 + grp;
                af[mt][0] = As[cur][m][ks + qp];
                af[mt][1] = As[cur][m + 8][ks + qp];
                af[mt][2] = As[cur][m][ks + qp + 4];
                af[mt][3] = As[cur][m + 8][ks + qp + 4];
            }
            #pragma unroll
            for (int nt = 0; nt < 4; nt++) {
                int n = nw + nt * 8 + grp;
                bf[nt][0] = Bs[cur][n][ks + qp];
                bf[nt][1] = Bs[cur][n][ks + qp + 4];
            }
            #pragma unroll
            for (int mt = 0; mt < 4; mt++)
                #pragma unroll
                for (int nt = 0; nt < 4; nt++)
                    mma_tf32(acc[mt][nt], af[mt], bf[nt]);
        }

        if (has_next) {
            const int nxt = cur ^ 1;
            uint4 ua0 = make_uint4(f2tf32(pa0.x), f2tf32(pa0.y), f2tf32(pa0.z), f2tf32(pa0.w));
            uint4 ua1 = make_uint4(f2tf32(pa1.x), f2tf32(pa1.y), f2tf32(pa1.z), f2tf32(pa1.w));
            uint4 ub0 = make_uint4(f2tf32(pb0.x), f2tf32(pb0.y), f2tf32(pb0.z), f2tf32(pb0.w));
            uint4 ub1 = make_uint4(f2tf32(pb1.x), f2tf32(pb1.y), f2tf32(pb1.z), f2tf32(pb1.w));
            *(uint4*)&As[nxt][lr][lc]     = ua0;
            *(uint4*)&As[nxt][lr][lc + 4] = ua1;
            *(uint4*)&Bs[nxt][lr][lc]     = ub0;
            *(uint4*)&Bs[nxt][lr][lc + 4] = ub1;
            __syncthreads();
        }
    }

    #pragma unroll
    for (int nt = 0; nt < 4; nt++) {
        int col = n0 + nw + nt * 8 + qp * 2;
        float b0 = bias[col], b1 = bias[col + 1];
        #pragma unroll
        for (int mt = 0; mt < 4; mt++) {
            int row0 = m0 + mw + mt * 16 + grp;
            float v0 = acc[mt][nt][0] + b0;
            float v1 = acc[mt][nt][1] + b1;
            float v2 = acc[mt][nt][2] + b0;
            float v3 = acc[mt][nt][3] + b1;
            if (ACT == 1) { v0 = gelu_exact(v0); v1 = gelu_exact(v1); v2 = gelu_exact(v2); v3 = gelu_exact(v3); }
            *(float2*)&C[(size_t)row0 * N + col]       = make_float2(v0, v1);
            *(float2*)&C[(size_t)(row0 + 8) * N + col] = make_float2(v2, v3);
        }
    }
}

// ---------------- MMA flash attention -----------------------------------------
// keep = (k < M) | (q == k). Reads qkv [ROWS][768] directly, writes merged
// output [ROWS][256]. CTA: 128 queries x one (b,h); 4 warps x 32 queries.
// Main loop over key chunks of 32 in [0,M); diagonal handled in epilogue.
__global__ __launch_bounds__(128)
void attn_mma(const float* __restrict__ qkv, const int* __restrict__ sep,
              float* __restrict__ out)
{
    const int h = blockIdx.y, b = blockIdx.z;
    const int q0 = blockIdx.x * 128;
    const int tid = threadIdx.x;
    const int w = tid >> 5, lane = tid & 31;
    const int grp = lane >> 2, qp = lane & 3;
    const int M_ = *sep;
    const float scale = 0.17677669529663687f;   // 1/sqrt(32)

    __shared__ float Ks [32][36];
    __shared__ float Vts[32][36];
    __shared__ float Ps [4][32][36];            // per-warp P tile; prologue: Q staging

    // ---- stage Q (128 rows x 32) into Ps area, then load fragments to regs ----
    float* Qst = &Ps[0][0][0];                  // [128][36] = 4608 floats = sizeof(Ps)
    {
        const size_t qbase = ((size_t)q0*4 + b)*768 + (size_t)h*32;
        #pragma unroll
        for (int i = 0; i < 8; i++) {
            int idx = i*128 + tid;              // 0..1023
            int r = idx >> 3, c4 = (idx & 7) * 4;
            float4 qv = *(const float4*)&qkv[qbase + (size_t)r*4*768 + c4];
            *(float4*)&Qst[r*36 + c4] = qv;
        }
    }
    __syncthreads();

    uint32_t qf[2][4][4];
    #pragma unroll
    for (int mt = 0; mt < 2; mt++)
        #pragma unroll
        for (int ks = 0; ks < 4; ks++) {
            int r = w*32 + mt*16 + grp;
            qf[mt][ks][0] = f2tf32(Qst[r*36 + ks*8 + qp]);
            qf[mt][ks][1] = f2tf32(Qst[(r+8)*36 + ks*8 + qp]);
            qf[mt][ks][2] = f2tf32(Qst[r*36 + ks*8 + qp + 4]);
            qf[mt][ks][3] = f2tf32(Qst[(r+8)*36 + ks*8 + qp + 4]);
        }
    // NOTE: first __syncthreads in the chunk loop separates these reads from P stores.

    float acc_o[2][4][4];
    #pragma unroll
    for (int mt = 0; mt < 2; mt++)
        #pragma unroll
        for (int nt = 0; nt < 4; nt++)
            #pragma unroll
            for (int e = 0; e < 4; e++) acc_o[mt][nt][e] = 0.f;
    float m_st[2][2] = {{-1e30f, -1e30f}, {-1e30f, -1e30f}};
    float l_st[2][2] = {{0.f, 0.f}, {0.f, 0.f}};

    const int nch = (M_ + 31) >> 5;
    for (int c = 0; c < nch; c++) {
        const int kbase = c * 32;
        __syncthreads();
        // load K chunk and V chunk (transposed) — 32 rows x 32 floats each
        #pragma unroll
        for (int i = 0; i < 2; i++) {
            int idx = i*128 + tid;              // 0..255
            int r = idx >> 3, c4 = (idx & 7) * 4;
            size_t gro = ((size_t)(kbase + r)*4 + b)*768 + (size_t)h*32 + c4;
            float4 kv = *(const float4*)&qkv[gro + 256];
            *(float4*)&Ks[r][c4] = kv;
            float4 vv = *(const float4*)&qkv[gro + 512];
            Vts[c4+0][r] = vv.x; Vts[c4+1][r] = vv.y;
            Vts[c4+2][r] = vv.z; Vts[c4+3][r] = vv.w;
        }
        __syncthreads();

        // ---- S = Q @ K^T (32q x 32k per warp) ----
        float acc_s[2][4][4];
        #pragma unroll
        for (int mt = 0; mt < 2; mt++)
            #pragma unroll
            for (int nt = 0; nt < 4; nt++)
                #pragma unroll
                for (int e = 0; e < 4; e++) acc_s[mt][nt][e] = 0.f;
        #pragma unroll
        for (int nt = 0; nt < 4; nt++)
            #pragma unroll
            for (int ks = 0; ks < 4; ks++) {
                uint32_t bf[2];
                bf[0] = f2tf32(Ks[nt*8 + grp][ks*8 + qp]);
                bf[1] = f2tf32(Ks[nt*8 + grp][ks*8 + qp + 4]);
                mma_tf32(acc_s[0][nt], qf[0][ks], bf);
                mma_tf32(acc_s[1][nt], qf[1][ks], bf);
            }

        // ---- online softmax update (per thread: 4 rows) ----
        #pragma unroll
        for (int mt = 0; mt < 2; mt++)
            #pragma unroll
            for (int hf = 0; hf < 2; hf++) {
                float sv[4][2];
                float mx = -1e30f;
                #pragma unroll
                for (int nt = 0; nt < 4; nt++)
                    #pragma unroll
                    for (int j = 0; j < 2; j++) {
                        float s = acc_s[mt][nt][hf*2 + j] * scale;
                        int key = kbase + nt*8 + 2*qp + j;
                        if (key >= M_) s = -1e30f;
                        sv[nt][j] = s;
                        mx = fmaxf(mx, s);
                    }
                mx = fmaxf(mx, __shfl_xor_sync(0xffffffffu, mx, 1));
                mx = fmaxf(mx, __shfl_xor_sync(0xffffffffu, mx, 2));
                float m_old = m_st[mt][hf];
                float m_new = fmaxf(m_old, mx);
                float alpha = __expf(m_old - m_new);
                float rs = 0.f;
                int prow = mt*16 + grp + hf*8;
                #pragma unroll
                for (int nt = 0; nt < 4; nt++) {
                    float p0 = __expf(sv[nt][0] - m_new);
                    float p1 = __expf(sv[nt][1] - m_new);
                    rs += p0 + p1;
                    float2 pp = make_float2(__uint_as_float(f2tf32(p0)),
                                            __uint_as_float(f2tf32(p1)));
                    *(float2*)&Ps[w][prow][nt*8 + 2*qp] = pp;
                }
                rs += __shfl_xor_sync(0xffffffffu, rs, 1);
                rs += __shfl_xor_sync(0xffffffffu, rs, 2);
                l_st[mt][hf] = l_st[mt][hf] * alpha + rs;
                m_st[mt][hf] = m_new;
                #pragma unroll
                for (int ntd = 0; ntd < 4; ntd++) {
                    acc_o[mt][ntd][hf*2 + 0] *= alpha;
                    acc_o[mt][ntd][hf*2 + 1] *= alpha;
                }
            }
        __syncwarp();

        // ---- O += P @ V ----
        #pragma unroll
        for (int ks = 0; ks < 4; ks++) {
            uint32_t af[2][4];
            #pragma unroll
            for (int mt = 0; mt < 2; mt++) {
                int r = mt*16 + grp;
                af[mt][0] = __float_as_uint(Ps[w][r][ks*8 + qp]);
                af[mt][1] = __float_as_uint(Ps[w][r + 8][ks*8 + qp]);
                af[mt][2] = __float_as_uint(Ps[w][r][ks*8 + qp + 4]);
                af[mt][3] = __float_as_uint(Ps[w][r + 8][ks*8 + qp + 4]);
            }
            #pragma unroll
            for (int ntd = 0; ntd < 4; ntd++) {
                uint32_t bf[2];
                bf[0] = f2tf32(Vts[ntd*8 + grp][ks*8 + qp]);
                bf[1] = f2tf32(Vts[ntd*8 + grp][ks*8 + qp + 4]);
                mma_tf32(acc_o[0][ntd], af[0], bf);
                mma_tf32(acc_o[1][ntd], af[1], bf);
            }
        }
    }

    // ---- diagonal key for q >= M ----
    #pragma unroll
    for (int mt = 0; mt < 2; mt++)
        #pragma unroll
        for (int hf = 0; hf < 2; hf++) {
            int q_g = q0 + w*32 + mt*16 + grp + hf*8;
            bool active = (q_g >= M_);
            float part = 0.f;
            size_t rbase = ((size_t)q_g*4 + b)*768 + (size_t)h*32;
            if (active) {
                #pragma unroll
                for (int ks = 0; ks < 4; ks++) {
                    float k0 = qkv[rbase + 256 + ks*8 + qp];
                    float k1 = qkv[rbase + 256 + ks*8 + qp + 4];
                    float qa = __uint_as_float(qf[mt][ks][hf ? 1 : 0]);
                    float qb = __uint_as_float(qf[mt][ks][hf ? 3 : 2]);
                    part += qa*k0 + qb*k1;
                }
            }
            part += __shfl_xor_sync(0xffffffffu, part, 1);
            part += __shfl_xor_sync(0xffffffffu, part, 2);
            if (active) {
                float s_d = part * scale;
                float m_old = m_st[mt][hf];
                float m_new = fmaxf(m_old, s_d);
                float alpha = __expf(m_old - m_new);
                float pd = __expf(s_d - m_new);
                l_st[mt][hf] = l_st[mt][hf] * alpha + pd;
                m_st[mt][hf] = m_new;
                #pragma unroll
                for (int ntd = 0; ntd < 4; ntd++) {
                    float v0 = qkv[rbase + 512 + ntd*8 + 2*qp];
                    float v1 = qkv[rbase + 512 + ntd*8 + 2*qp + 1];
                    acc_o[mt][ntd][hf*2 + 0] = acc_o[mt][ntd][hf*2 + 0]*alpha + pd*v0;
                    acc_o[mt][ntd][hf*2 + 1] = acc_o[mt][ntd][hf*2 + 1]*alpha + pd*v1;
                }
            }
        }

    // ---- finalize: O /= l, store merged [row][h*32+d] ----
    #pragma unroll
    for (int mt = 0; mt < 2; mt++)
        #pragma unroll
        for (int hf = 0; hf < 2; hf++) {
            int q_g = q0 + w*32 + mt*16 + grp + hf*8;
            size_t orow = ((size_t)q_g*4 + b)*256 + (size_t)h*32;
            float inv = 1.f / l_st[mt][hf];
            #pragma unroll
            for (int ntd = 0; ntd < 4; ntd++) {
                float2 o2 = make_float2(acc_o[mt][ntd][hf*2 + 0] * inv,
                                        acc_o[mt][ntd][hf*2 + 1] * inv);
                *(float2*)&out[orow + ntd*8 + 2*qp] = o2;
            }
        }
}

// ---------------- residual add + layer norm ----------------------------------
__global__ void add_ln_kernel(const float* __restrict__ resid,
                              const float* __restrict__ delta,
                              const float* __restrict__ g, const float* __restrict__ bb,
                              float* __restrict__ out)
{
    int row = blockIdx.x;
    int d = threadIdx.x;
    __shared__ float red[DM];
    __shared__ float mu_s, rstd_s;
    float v = resid[(size_t)row*DM + d] + delta[(size_t)row*DM + d];
    red[d] = v;
    __syncthreads();
    for (int off = 128; off > 0; off >>= 1) {
        if (d < off) red[d] += red[d + off];
        __syncthreads();
    }
    if (d == 0) mu_s = red[0] * (1.0f / DM);
    __syncthreads();
    float mu = mu_s;
    float c = v - mu;
    red[d] = c * c;
    __syncthreads();
    for (int off = 128; off > 0; off >>= 1) {
        if (d < off) red[d] += red[d + off];
        __syncthreads();
    }
    if (d == 0) rstd_s = rsqrtf(red[0] * (1.0f / DM) + 1e-5f);
    __syncthreads();
    out[(size_t)row*DM + d] = c * rstd_s * g[d] + bb[d];
}

// ---------------- final head: out[(s-M)*B+b] = hid . w2 + b2 -----------------
__global__ void head2_kernel(const float* __restrict__ hid, const float* __restrict__ w2,
                             const float* __restrict__ b2, const int* __restrict__ sep,
                             float* __restrict__ out)
{
    int row = blockIdx.x;
    int M_ = *sep;
    int s = row >> 2, b = row & 3;
    if (s < M_) return;
    float sum = 0.f;
    for (int t = threadIdx.x; t < DFF; t += 128)
        sum += hid[(size_t)row*DFF + t] * w2[t];
    for (int off = 16; off > 0; off >>= 1)
        sum += __shfl_down_sync(0xffffffffu, sum, off);
    __shared__ float ws[4];
    if ((threadIdx.x & 31) == 0) ws[threadIdx.x >> 5] = sum;
    __syncthreads();
    if (threadIdx.x == 0)
        out[(s - M_)*BT + b] = ws[0] + ws[1] + ws[2] + ws[3] + b2[0];
}

// =============================================================================
extern "C" void kernel_launch(void* const* d_in, const int* in_sizes, int n_in,
                              void* d_out, int out_size)
{
    (void)in_sizes; (void)n_in; (void)out_size;
    const float* x        = (const float*)d_in[0];
    const float* y        = (const float*)d_in[1];
    const int*   sep      = (const int*  )d_in[2];
    const float* xenc_w   = (const float*)d_in[3];
    const float* xenc_b   = (const float*)d_in[4];
    const float* yenc_w   = (const float*)d_in[5];
    const float* yenc_b   = (const float*)d_in[6];
    const float* in_proj_w= (const float*)d_in[7];
    const float* in_proj_b= (const float*)d_in[8];
    const float* out_proj_w=(const float*)d_in[9];
    const float* out_proj_b=(const float*)d_in[10];
    const float* ln1_g    = (const float*)d_in[11];
    const float* ln1_b    = (const float*)d_in[12];
    const float* lin1_w   = (const float*)d_in[13];
    const float* lin1_b   = (const float*)d_in[14];
    const float* lin2_w   = (const float*)d_in[15];
    const float* lin2_b   = (const float*)d_in[16];
    const float* ln2_g    = (const float*)d_in[17];
    const float* ln2_b    = (const float*)d_in[18];
    const float* head_w1  = (const float*)d_in[19];
    const float* head_b1  = (const float*)d_in[20];
    const float* head_w2  = (const float*)d_in[21];
    const float* head_b2  = (const float*)d_in[22];
    float* out = (float*)d_out;

    float *h, *qkv, *tmp, *tmp2, *ff;
    cudaGetSymbolAddress((void**)&h,    g_h);
    cudaGetSymbolAddress((void**)&qkv,  g_qkv);
    cudaGetSymbolAddress((void**)&tmp,  g_tmp);
    cudaGetSymbolAddress((void**)&tmp2, g_tmp2);
    cudaGetSymbolAddress((void**)&ff,   g_ff);

    embed_kernel<<<ROWS, DM>>>(x, y, sep, xenc_w, xenc_b, yenc_w, yenc_b, h);

    for (int l = 0; l < NL; l++) {
        gemm_tc<0><<<dim3(3*DM/128, ROWS/128), 256>>>(
            h, in_proj_w + (size_t)l*3*DM*DM, in_proj_b + (size_t)l*3*DM, qkv, 3*DM, DM, nullptr);
        attn_mma<<<dim3(SEQ/128, NHD, BT), 128>>>(qkv, sep, tmp);
        gemm_tc<0><<<dim3(DM/128, ROWS/128), 256>>>(
            tmp, out_proj_w + (size_t)l*DM*DM, out_proj_b + (size_t)l*DM, tmp2, DM, DM, nullptr);
        add_ln_kernel<<<ROWS, DM>>>(h, tmp2, ln1_g + (size_t)l*DM, ln1_b + (size_t)l*DM, h);
        gemm_tc<1><<<dim3(DFF/128, ROWS/128), 256>>>(
            h, lin1_w + (size_t)l*DFF*DM, lin1_b + (size_t)l*DFF, ff, DFF, DM, nullptr);
        gemm_tc<0><<<dim3(DM/128, ROWS/128), 256>>>(
            ff, lin2_w + (size_t)l*DM*DFF, lin2_b + (size_t)l*DM, tmp2, DM, DFF, nullptr);
        add_ln_kernel<<<ROWS, DM>>>(h, tmp2, ln2_g + (size_t)l*DM, ln2_b + (size_t)l*DM, h);
    }

    gemm_tc<1><<<dim3(DFF/128, ROWS/128), 256>>>(h, head_w1, head_b1, ff, DFF, DM, sep);
    head2_kernel<<<ROWS, 128>>>(ff, head_w2, head_b2, sep, out);
}